// round 14
// baseline (speedup 1.0000x reference)
#include <cuda_runtime.h>
#include <cuda_fp16.h>
#include <cstdint>

#define BATCH 8
#define CCH   128
#define HH    128
#define WW    256
#define KS    9
#define NTOT  (BATCH*CCH*HH*WW)

__device__ float g_tmp[NTOT];                        // transposed scratch
// halo buffers: [b][tile][side][parity][4 rows][128 ci] fp16
__device__ __align__(16) __half g_halo[BATCH][8][2][2][4][128];
// per-(pass,b,tile,cog) step flags, padded 32B
__device__ unsigned g_flags[4][BATCH][8][4][8];

__device__ __forceinline__ unsigned ld_acq(const unsigned* p) {
    unsigned v;
    asm volatile("ld.acquire.gpu.global.u32 %0, [%1];" : "=r"(v) : "l"(p) : "memory");
    return v;
}
__device__ __forceinline__ void st_rel(unsigned* p, unsigned v) {
    asm volatile("st.release.gpu.global.u32 [%0], %1;" :: "l"(p), "r"(v) : "memory");
}
__device__ __forceinline__ uint32_t smem_u32(const void* p) {
    uint32_t a;
    asm("{ .reg .u64 t; cvta.to.shared.u64 t, %1; cvt.u32.u64 %0, t; }"
        : "=r"(a) : "l"(p));
    return a;
}
__device__ __forceinline__ uint32_t mapa_peer(uint32_t addr, uint32_t rank) {
    uint32_t r;
    asm("mapa.shared::cluster.u32 %0, %1, %2;" : "=r"(r) : "r"(addr), "r"(rank));
    return r;
}
__device__ __forceinline__ void st_dsmem(uint32_t addr, uint32_t v) {
    asm volatile("st.shared::cluster.u32 [%0], %1;" :: "r"(addr), "r"(v) : "memory");
}
__device__ __forceinline__ void sts32(uint32_t addr, uint32_t v) {
    asm volatile("st.shared.u32 [%0], %1;" :: "r"(addr), "r"(v) : "memory");
}
__device__ __forceinline__ void cluster_sync() {
    asm volatile("barrier.cluster.arrive.aligned;" ::: "memory");
    asm volatile("barrier.cluster.wait.aligned;" ::: "memory");
}
__device__ __forceinline__ uint32_t ctarank() {
    uint32_t r; asm("mov.u32 %0, %%cluster_ctarank;" : "=r"(r)); return r;
}
__device__ __forceinline__ void cp16(uint32_t d, const void* s) {
    asm volatile("cp.async.cg.shared.global [%0], [%1], 16;" :: "r"(d), "l"(s));
}
__device__ __forceinline__ void ldsm4(uint32_t addr, uint32_t& r0, uint32_t& r1,
                                      uint32_t& r2, uint32_t& r3) {
    asm volatile("ldmatrix.sync.aligned.m8n8.x4.shared.b16 {%0,%1,%2,%3}, [%4];"
                 : "=r"(r0), "=r"(r1), "=r"(r2), "=r"(r3) : "r"(addr));
}
__device__ __forceinline__ void ldsm2(uint32_t addr, uint32_t& r0, uint32_t& r1) {
    asm volatile("ldmatrix.sync.aligned.m8n8.x2.shared.b16 {%0,%1}, [%2];"
                 : "=r"(r0), "=r"(r1) : "r"(addr));
}
__device__ __forceinline__ void mma_f16(float* c, const uint32_t* a,
                                        uint32_t b0, uint32_t b1) {
    asm volatile(
        "mma.sync.aligned.m16n8k16.row.col.f32.f16.f16.f32 "
        "{%0,%1,%2,%3}, {%4,%5,%6,%7}, {%8,%9}, {%0,%1,%2,%3};"
        : "+f"(c[0]), "+f"(c[1]), "+f"(c[2]), "+f"(c[3])
        : "r"(a[0]), "r"(a[1]), "r"(a[2]), "r"(a[3]), "r"(b0), "r"(b1));
}
__device__ __forceinline__ uint32_t h2u(__half a, __half b) {
    __half2 t = __halves2half2(a, b);
    return *reinterpret_cast<uint32_t*>(&t);
}

// ---------------------------------------------------------------------------
// Cluster(4) persistent pass kernel, occupancy 2, fp16 single-term.
// CTA = (co-group 32, l-tile M, batch); the 4 co-groups of a tile form a
// cluster. 128 threads / 4 warps; warp = one n8 co-subgroup, covers all mt.
// Carry in smem: own 32-ci slice direct; other 96 ci via DSMEM stores to 3
// peers + one cluster_sync per step. +-4 column l-halos: global buffers +
// per-cog flags (poll 4 flags per side). Two CTAs co-resident per SM hide
// the per-step sync scaffolding of each other's independent chains.
// out[l,co] = x + relu( sum_{ci,k} w[co,ci,k]*prev[ci,l+k-4] )
// ---------------------------------------------------------------------------
template<int S, int L, int M>
__global__ void __cluster_dims__(4, 1, 1) __launch_bounds__(128, 2)
pass_kernel(float* __restrict__ buf, const float* __restrict__ wgt,
            unsigned* __restrict__ flags, int reverse)
{
    constexpr int ROWS  = M + 8;
    constexpr int AST   = 136;                  // A/W row stride (halfs)
    constexpr int ASIZE = ROWS * AST * 2;       // bytes per parity
    constexpr int SM_W  = 2 * ASIZE;
    constexpr int MT    = M / 16;               // m16 tiles (2 V, 1 H)

    extern __shared__ char sm[];
    const uint32_t smb = smem_u32(sm);
    const uint32_t smW = smb + SM_W;

    const int tid  = threadIdx.x;
    const int wid  = tid >> 5;
    const int lane = tid & 31;
    const int cog  = blockIdx.x;                 // cluster rank
    const int tile = blockIdx.y;
    const int b    = blockIdx.z;
    const int l0   = tile * M;
    const int co0  = cog * 32;

    const uint32_t rank = ctarank();
    uint32_t rpeer[3];
    { int j = 0;
      for (int p = 0; p < 4; ++p) if (p != (int)rank) rpeer[j++] = mapa_peer(smb, p); }

    float* base = buf + (size_t)b * CCH * S * L;
    unsigned* fown = flags + (((b * 8 + tile) * 4 + cog) * 8);
    unsigned* mypoll = nullptr;
    if (tid < 8) {
        int side = tid >> 2, c = tid & 3;
        int nt = side ? tile + 1 : tile - 1;
        if (nt >= 0 && nt < 8) mypoll = flags + (((b * 8 + nt) * 4 + c) * 8);
    }

    // ---- resident weights: wgt[co0+co][ci][k] -> W[tap*32+co][ci] fp16 ----
    {
        __half* W = (__half*)(sm + SM_W);
        for (int idx = tid; idx < 32 * CCH * KS; idx += 128) {
            int co = idx / (CCH * KS);
            int r  = idx % (CCH * KS);
            int ci = r / KS;
            int k  = r % KS;
            float v = wgt[(size_t)(co0 + co) * CCH * KS + (size_t)ci * KS + k];
            W[(k * 32 + co) * AST + ci] = __float2half_rn(v);
        }
    }
    // ---- zero A (both parities), then fill A[par0] with x row s0 window ----
    for (int idx = tid; idx < 2 * ASIZE / 4; idx += 128)
        ((uint32_t*)sm)[idx] = 0u;
    __syncthreads();
    {
        const int s0 = reverse ? (S - 1) : 0;
        const float* src = base + (size_t)s0 * L;
        __half* A0 = (__half*)sm;                // parity 0
        for (int idx = tid; idx < CCH * ROWS; idx += 128) {
            int ci = idx / ROWS;
            int r  = idx % ROWS;
            int gl = l0 - 4 + r;
            float v = (gl >= 0 && gl < L) ? src[(size_t)ci * S * L + gl] : 0.0f;
            A0[r * AST + ci] = __float2half_rn(v);
        }
    }
    __syncthreads();
    cluster_sync();     // peers' A zero/init done before any DSMEM writes land

    // lane mappings
    const int lt    = lane >> 3;
    const int lrow  = (lane & 7) + ((lt & 1) << 3);
    const int lk    = (lt >> 1) << 3;
    const int l2row = lane & 7;
    const int l2k   = ((lane >> 3) & 1) << 3;
    const int r4    = lane >> 2;
    const int cp2   = (lane & 3) * 2;
    const int coL   = wid * 8 + cp2;             // local co (0..31)
    const int ciG   = co0 + coL;                 // global ci column in A

    for (int i = 1; i < S; ++i) {
        const int s_cur = reverse ? (S - 1 - i) : i;
        const int pprev = (i - 1) & 1;
        const int pcur  = i & 1;
        const uint32_t aB = smb + (uint32_t)pprev * ASIZE;

        // ---- x loads straight to registers (consumed at epilogue) ----
        float xv[MT][2][2];
#pragma unroll
        for (int mt = 0; mt < MT; ++mt)
#pragma unroll
            for (int h2 = 0; h2 < 2; ++h2) {
                const int ll = mt * 16 + r4 + h2 * 8;
                xv[mt][h2][0] = base[((size_t)(co0 + coL) * S + s_cur) * L + l0 + ll];
                xv[mt][h2][1] = base[((size_t)(co0 + coL + 1) * S + s_cur) * L + l0 + ll];
            }

        float acc[MT][4];
#pragma unroll
        for (int mt = 0; mt < MT; ++mt)
#pragma unroll
            for (int e = 0; e < 4; ++e) acc[mt][e] = 0.0f;

        auto do_tap = [&](int tap, bool m0, bool m1) {
#pragma unroll
            for (int kc = 0; kc < 8; ++kc) {
                uint32_t b0, b1;
                ldsm2(smW + (uint32_t)(((tap * 32 + wid * 8 + l2row) * AST
                                        + kc * 16 + l2k) * 2), b0, b1);
                uint32_t a[4];
                if (m0) {
                    ldsm4(aB + (uint32_t)(((tap + lrow) * AST + kc * 16 + lk) * 2),
                          a[0], a[1], a[2], a[3]);
                    mma_f16(acc[0], a, b0, b1);
                }
                if (MT == 2 && m1) {
                    ldsm4(aB + (uint32_t)(((16 + tap + lrow) * AST + kc * 16 + lk) * 2),
                          a[0], a[1], a[2], a[3]);
                    mma_f16(acc[1], a, b0, b1);
                }
            }
        };

        // ---- phase 1: interior (mt,tap) pairs ----
        if constexpr (MT == 2) {
#pragma unroll
            for (int t = 0; t < 4; ++t) do_tap(t, false, true);
            do_tap(4, true, true);
#pragma unroll
            for (int t = 5; t < 9; ++t) do_tap(t, true, false);
        } else {
            do_tap(4, true, false);
        }

        // ---- wait l-neighbors (8 flags), pull 4-col halos into A[pprev] ----
        if (i >= 2) {
            if (tid < 8 && mypoll)
                while (ld_acq(mypoll) < (unsigned)(i - 1)) __nanosleep(16);
            __syncthreads();
            {
                const int s = tid >> 6;            // 0 = left, 1 = right
                const int r = (tid >> 4) & 3;
                const int c = tid & 15;
                const bool have = (s == 0) ? (tile > 0) : (tile < 7);
                if (have) {
                    const __half* src = &g_halo[b][s == 0 ? tile - 1 : tile + 1]
                                               [s == 0 ? 1 : 0][pprev][r][c * 8];
                    uint32_t dst = aB
                        + (uint32_t)(((s == 0 ? r : M + 4 + r) * AST + c * 8) * 2);
                    cp16(dst, src);
                }
            }
            asm volatile("cp.async.commit_group;" ::: "memory");
            asm volatile("cp.async.wait_group 0;" ::: "memory");
            __syncthreads();
        }

        // ---- phase 2: halo (mt,tap) pairs ----
        if constexpr (MT == 2) {
#pragma unroll
            for (int t = 0; t < 4; ++t) do_tap(t, true, false);
#pragma unroll
            for (int t = 5; t < 9; ++t) do_tap(t, false, true);
        } else {
#pragma unroll
            for (int t = 0; t < 4; ++t) do_tap(t, true, false);
#pragma unroll
            for (int t = 5; t < 9; ++t) do_tap(t, true, false);
        }

        // ---- epilogue p1: o = x + relu(acc); own A + 3 peers' A + halo ----
        float osav[MT][2][2];
        {
            const uint32_t oA = (uint32_t)pcur * ASIZE;
#pragma unroll
            for (int mt = 0; mt < MT; ++mt) {
#pragma unroll
                for (int h2 = 0; h2 < 2; ++h2) {
                    const int ll = mt * 16 + r4 + h2 * 8;
                    float o0 = xv[mt][h2][0] + fmaxf(acc[mt][h2 * 2 + 0], 0.0f);
                    float o1 = xv[mt][h2][1] + fmaxf(acc[mt][h2 * 2 + 1], 0.0f);
                    osav[mt][h2][0] = o0;
                    osav[mt][h2][1] = o1;
                    uint32_t hi2 = h2u(__float2half_rn(o0), __float2half_rn(o1));
                    const uint32_t aoff = (uint32_t)(((ll + 4) * AST + ciG) * 2);
                    sts32(smb + oA + aoff, hi2);
                    st_dsmem(rpeer[0] + oA + aoff, hi2);
                    st_dsmem(rpeer[1] + oA + aoff, hi2);
                    st_dsmem(rpeer[2] + oA + aoff, hi2);
                    if (ll < 4)
                        *(uint32_t*)&g_halo[b][tile][0][pcur][ll][ciG] = hi2;
                    if (ll >= M - 4)
                        *(uint32_t*)&g_halo[b][tile][1][pcur][ll - (M - 4)][ciG] = hi2;
                }
            }
        }

        __syncthreads();                      // halo/smem stores issued CTA-wide
        if (i <= S - 2 && tid == 0) st_rel(fown, (unsigned)i);

        // ---- epilogue p2: deferred buf STG (off the inter-CTA path) ----
#pragma unroll
        for (int mt = 0; mt < MT; ++mt)
#pragma unroll
            for (int h2 = 0; h2 < 2; ++h2) {
                const int ll = mt * 16 + r4 + h2 * 8;
                base[((size_t)(co0 + coL) * S + s_cur) * L + l0 + ll]     = osav[mt][h2][0];
                base[((size_t)(co0 + coL + 1) * S + s_cur) * L + l0 + ll] = osav[mt][h2][1];
            }

        cluster_sync();                       // DSMEM A[pcur] visible clusterwide
    }
}

// ---------------------------------------------------------------------------
// Transpose [P, A, B] -> [P, B, A]
// ---------------------------------------------------------------------------
__global__ void transpose_kernel(const float* __restrict__ in,
                                 float* __restrict__ out, int A, int B)
{
    __shared__ float tile[32][33];
    const size_t p = blockIdx.z;
    const int b0 = blockIdx.x * 32;
    const int a0 = blockIdx.y * 32;
    const int tx = threadIdx.x, ty = threadIdx.y;
    const float* ip = in  + p * (size_t)A * B;
    float*       op = out + p * (size_t)A * B;
#pragma unroll
    for (int i = ty; i < 32; i += 8)
        tile[i][tx] = ip[(size_t)(a0+i)*B + (b0+tx)];
    __syncthreads();
#pragma unroll
    for (int i = ty; i < 32; i += 8)
        op[(size_t)(b0+i)*A + (a0+tx)] = tile[tx][i];
}

// Vertical: [B,C,S=H=128,L=W=256], M=32 (8 tiles). Horizontal: S=256,L=128, M=16.
#define PASSV pass_kernel<128,256,32>
#define PASSH pass_kernel<256,128,16>

static constexpr int SMEM_V = 2*(40*136*2) + KS*32*136*2;  // 21760+78336=100096
static constexpr int SMEM_H = 2*(24*136*2) + KS*32*136*2;  // 13056+78336= 91392

extern "C" void kernel_launch(void* const* d_in, const int* in_sizes, int n_in,
                              void* d_out, int out_size)
{
    const float* x    = (const float*)d_in[0];
    const float* w_ud = (const float*)d_in[1];
    const float* w_du = (const float*)d_in[2];
    const float* w_lr = (const float*)d_in[3];
    const float* w_rl = (const float*)d_in[4];
    float* buf = (float*)d_out;

    float* tbuf = nullptr;
    cudaGetSymbolAddress((void**)&tbuf, g_tmp);
    unsigned* flags = nullptr;
    cudaGetSymbolAddress((void**)&flags, g_flags);

    cudaFuncSetAttribute(PASSV, cudaFuncAttributeMaxDynamicSharedMemorySize, SMEM_V);
    cudaFuncSetAttribute(PASSH, cudaFuncAttributeMaxDynamicSharedMemorySize, SMEM_H);

    cudaMemsetAsync(flags, 0, 4 * BATCH * 8 * 4 * 8 * sizeof(unsigned), 0);
    cudaMemcpyAsync(buf, x, (size_t)NTOT * sizeof(float),
                    cudaMemcpyDeviceToDevice, 0);

    const unsigned PSTRIDE = BATCH * 8 * 4 * 8;

    dim3 g(4, 8, BATCH);   // 256 CTAs = 64 clusters of 4, occ 2, all resident
    PASSV<<<g, 128, SMEM_V>>>(buf, w_ud, flags + 0*PSTRIDE, 0);
    PASSV<<<g, 128, SMEM_V>>>(buf, w_du, flags + 1*PSTRIDE, 1);

    transpose_kernel<<<dim3(WW/32, HH/32, BATCH*CCH), dim3(32,8)>>>(buf, tbuf, HH, WW);

    PASSH<<<g, 128, SMEM_H>>>(tbuf, w_lr, flags + 2*PSTRIDE, 0);
    PASSH<<<g, 128, SMEM_H>>>(tbuf, w_rl, flags + 3*PSTRIDE, 1);

    transpose_kernel<<<dim3(HH/32, WW/32, BATCH*CCH), dim3(32,8)>>>(tbuf, buf, WW, HH);
}